// round 1
// baseline (speedup 1.0000x reference)
#include <cuda_runtime.h>
#include <math.h>

#define B_  2
#define S_  4096
#define D_  768
#define H_  12
#define HD_ 64
#define M_  (B_ * S_)   // 8192

// Scratch buffers (allocation-free rule: __device__ globals)
__device__ float gQ[(size_t)B_ * H_ * S_ * HD_];   // [B,H,S,HD], pre-scaled by 1/8
__device__ float gK[(size_t)B_ * H_ * S_ * HD_];   // [B,H,S,HD]
__device__ float gV[(size_t)B_ * H_ * S_ * HD_];   // [B,H,S,HD]
__device__ float gCtx[(size_t)B_ * S_ * D_];       // [B,S,D]

// ---------------------------------------------------------------------------
// SGEMM: out = (X @ W^T + bias) * scale
//   X: [M_, D_] row-major, W: [D_, D_] row-major (torch Linear weight),
//   so C[m,n] = sum_k X[m,k] * W[n,k].
// scatter=1: write to [B,H,S,HD] layout (n = h*64+hd, m = b*4096+s)
// scatter=0: write row-major [M_, D_]
// Tiles: 64x64x16, 256 threads, 4x4 microtile, float4 smem reads.
// ---------------------------------------------------------------------------
__global__ void __launch_bounds__(256) gemm_kernel(
    const float* __restrict__ X, const float* __restrict__ W,
    const float* __restrict__ bias, float* __restrict__ out,
    float scale, int scatter)
{
    __shared__ float As[16][64];   // As[k][m]  (transposed X tile)
    __shared__ float Bs[16][64];   // Bs[k][n]  (transposed W tile)

    const int tid = threadIdx.x;
    const int tx  = tid & 15;      // 0..15 -> n microtile
    const int ty  = tid >> 4;      // 0..15 -> m microtile
    const int m0  = blockIdx.y << 6;
    const int n0  = blockIdx.x << 6;

    // load indexing: each thread loads one float4 of X and one of W per k-tile
    const int lr = tid >> 2;             // 0..63 row within tile
    const int lc = (tid & 3) << 2;       // 0,4,8,12 k-offset
    const float* xp = X + (size_t)(m0 + lr) * D_ + lc;
    const float* wp = W + (size_t)(n0 + lr) * D_ + lc;

    float acc[4][4] = {};

    for (int k0 = 0; k0 < D_; k0 += 16) {
        float4 xa = *(const float4*)(xp + k0);
        float4 wb = *(const float4*)(wp + k0);
        As[lc + 0][lr] = xa.x; As[lc + 1][lr] = xa.y;
        As[lc + 2][lr] = xa.z; As[lc + 3][lr] = xa.w;
        Bs[lc + 0][lr] = wb.x; Bs[lc + 1][lr] = wb.y;
        Bs[lc + 2][lr] = wb.z; Bs[lc + 3][lr] = wb.w;
        __syncthreads();

#pragma unroll
        for (int k = 0; k < 16; k++) {
            const float4 a4 = *(const float4*)&As[k][ty << 2];
            const float4 b4 = *(const float4*)&Bs[k][tx << 2];
            const float a[4] = {a4.x, a4.y, a4.z, a4.w};
            const float b[4] = {b4.x, b4.y, b4.z, b4.w};
#pragma unroll
            for (int i = 0; i < 4; i++)
#pragma unroll
                for (int j = 0; j < 4; j++)
                    acc[i][j] = fmaf(a[i], b[j], acc[i][j]);
        }
        __syncthreads();
    }

    // bias (loaded once per thread)
    float bb[4];
#pragma unroll
    for (int j = 0; j < 4; j++) bb[j] = bias[n0 + (tx << 2) + j];

#pragma unroll
    for (int i = 0; i < 4; i++) {
        const int m = m0 + (ty << 2) + i;
#pragma unroll
        for (int j = 0; j < 4; j++) {
            const int n = n0 + (tx << 2) + j;
            const float v = (acc[i][j] + bb[j]) * scale;
            if (scatter) {
                const int b_  = m >> 12;        // m / 4096
                const int s_  = m & 4095;
                const int h_  = n >> 6;
                const int hd_ = n & 63;
                gQ[0]; // no-op, keeps compiler honest about globals
                out[(((size_t)(b_ * H_ + h_) * S_ + s_) << 6) + hd_] = v;
            } else {
                out[(size_t)m * D_ + n] = v;
            }
        }
    }
}

// ---------------------------------------------------------------------------
// Flash attention, causal, fp32. One CTA per (b,h, 64-row q-tile).
// Q pre-scaled by 1/8. Online softmax, O accumulated in registers (4x4/thread).
// smem: Qt[hd][q] (stride 64), Kt[hd][kv] (stride 64), Vs[kv][hd] (stride 64),
//       Ps[q][kv] (stride 68), mrow/lrow/crow[64].
// ---------------------------------------------------------------------------
#define PS_STRIDE 68
#define ATTN_SMEM_FLOATS (3 * 64 * 64 + 64 * PS_STRIDE + 3 * 64)
#define ATTN_SMEM_BYTES  (ATTN_SMEM_FLOATS * 4)

__global__ void __launch_bounds__(256) attn_kernel(
    const float* __restrict__ Qg, const float* __restrict__ Kg,
    const float* __restrict__ Vg, float* __restrict__ ctx)
{
    extern __shared__ float sm[];
    float* Qt   = sm;                        // 64*64, [hd][q]
    float* Kt   = Qt + 64 * 64;              // 64*64, [hd][kv]
    float* Vs   = Kt + 64 * 64;              // 64*64, [kv][hd]
    float* Ps   = Vs + 64 * 64;              // 64*PS_STRIDE, [q][kv]
    float* mrow = Ps + 64 * PS_STRIDE;
    float* lrow = mrow + 64;
    float* crow = lrow + 64;

    const int tid = threadIdx.x;
    const int tx  = tid & 15;
    const int ty  = tid >> 4;
    const int bh  = blockIdx.y;                       // 0..23
    const int qt  = (int)(gridDim.x - 1) - (int)blockIdx.x;  // longest first

    const float* Qp = Qg + ((size_t)bh * S_ + (size_t)qt * 64) * HD_;
    const float* Kp = Kg + (size_t)bh * S_ * HD_;
    const float* Vp = Vg + (size_t)bh * S_ * HD_;

    // --- load Q transposed: lane-per-row indexing -> conflict-free stores ---
    {
        const int rr = tid & 63;
        const int cb = (tid >> 6) << 4;   // 0,16,32,48
        const float* qp = Qp + (size_t)rr * HD_ + cb;
#pragma unroll
        for (int u = 0; u < 4; u++) {
            const float4 f = *(const float4*)(qp + u * 4);
            const int c = cb + u * 4;
            Qt[(c + 0) * 64 + rr] = f.x;
            Qt[(c + 1) * 64 + rr] = f.y;
            Qt[(c + 2) * 64 + rr] = f.z;
            Qt[(c + 3) * 64 + rr] = f.w;
        }
    }
    if (tid < 64) { mrow[tid] = -INFINITY; lrow[tid] = 0.0f; }

    float o[4][4] = {};
    __syncthreads();

    const int ntiles = qt + 1;
    for (int t = 0; t < ntiles; t++) {
        // --- load K (transposed) and V (row-major) tiles ---
        {
            const int rr = tid & 63;
            const int cb = (tid >> 6) << 4;
            const float* kp = Kp + ((size_t)(t * 64 + rr)) * HD_ + cb;
#pragma unroll
            for (int u = 0; u < 4; u++) {
                const float4 f = *(const float4*)(kp + u * 4);
                const int c = cb + u * 4;
                Kt[(c + 0) * 64 + rr] = f.x;
                Kt[(c + 1) * 64 + rr] = f.y;
                Kt[(c + 2) * 64 + rr] = f.z;
                Kt[(c + 3) * 64 + rr] = f.w;
            }
        }
        for (int i = tid; i < 64 * 16; i += 256) {
            const int r = i >> 4;
            const int c = (i & 15) << 2;
            const float4 f = *(const float4*)(Vp + ((size_t)(t * 64 + r)) * HD_ + c);
            *(float4*)&Vs[r * 64 + c] = f;
        }
        __syncthreads();

        // --- S = Q K^T (Q already has the 1/sqrt(hd) scale) ---
        float s[4][4] = {};
#pragma unroll 4
        for (int hd = 0; hd < HD_; hd++) {
            const float4 a4 = *(const float4*)&Qt[hd * 64 + (ty << 2)];
            const float4 b4 = *(const float4*)&Kt[hd * 64 + (tx << 2)];
            const float a[4] = {a4.x, a4.y, a4.z, a4.w};
            const float b[4] = {b4.x, b4.y, b4.z, b4.w};
#pragma unroll
            for (int i = 0; i < 4; i++)
#pragma unroll
                for (int j = 0; j < 4; j++)
                    s[i][j] = fmaf(a[i], b[j], s[i][j]);
        }

        // --- causal mask (only the diagonal tile needs it) + store P ---
        const bool diag = (t == qt);
#pragma unroll
        for (int i = 0; i < 4; i++) {
            const int qr = (ty << 2) + i;
            float4 st;
            float* sv = (float*)&st;
#pragma unroll
            for (int j = 0; j < 4; j++) {
                const int kc = (tx << 2) + j;
                sv[j] = (diag && kc > qr) ? -INFINITY : s[i][j];
            }
            *(float4*)&Ps[qr * PS_STRIDE + (tx << 2)] = st;
        }
        __syncthreads();

        // --- online softmax: 4 lanes per row, 16-col segments ---
        {
            const int r   = tid >> 2;
            const int seg = tid & 3;
            float* prow = Ps + r * PS_STRIDE + seg * 16;
            float mx = prow[0];
#pragma unroll
            for (int c = 1; c < 16; c++) mx = fmaxf(mx, prow[c]);
            mx = fmaxf(mx, __shfl_xor_sync(0xffffffffu, mx, 1));
            mx = fmaxf(mx, __shfl_xor_sync(0xffffffffu, mx, 2));
            const float mold = mrow[r];
            const float mnew = fmaxf(mold, mx);
            float sum = 0.0f;
#pragma unroll
            for (int c = 0; c < 16; c++) {
                const float p = __expf(prow[c] - mnew);
                prow[c] = p;
                sum += p;
            }
            sum += __shfl_xor_sync(0xffffffffu, sum, 1);
            sum += __shfl_xor_sync(0xffffffffu, sum, 2);
            if (seg == 0) {
                const float cf = __expf(mold - mnew);   // 0 if mold == -inf
                crow[r] = cf;
                lrow[r] = lrow[r] * cf + sum;
                mrow[r] = mnew;
            }
        }
        __syncthreads();

        // --- rescale O, then O += P V ---
        float cf[4];
#pragma unroll
        for (int i = 0; i < 4; i++) cf[i] = crow[(ty << 2) + i];
#pragma unroll
        for (int i = 0; i < 4; i++)
#pragma unroll
            for (int j = 0; j < 4; j++) o[i][j] *= cf[i];

#pragma unroll 4
        for (int kv = 0; kv < 64; kv++) {
            const float4 b4 = *(const float4*)&Vs[kv * 64 + (tx << 2)];
            const float b[4] = {b4.x, b4.y, b4.z, b4.w};
            float a[4];
#pragma unroll
            for (int i = 0; i < 4; i++) a[i] = Ps[((ty << 2) + i) * PS_STRIDE + kv];
#pragma unroll
            for (int i = 0; i < 4; i++)
#pragma unroll
                for (int j = 0; j < 4; j++)
                    o[i][j] = fmaf(a[i], b[j], o[i][j]);
        }
        __syncthreads();   // protect Kt/Vs/Ps before next tile
    }

    // --- normalize and write ctx in [B,S,D] (D index = h*64+hd) ---
    const int b_ = bh / H_;
    const int h_ = bh % H_;
#pragma unroll
    for (int i = 0; i < 4; i++) {
        const int r = (ty << 2) + i;
        const float inv = 1.0f / lrow[r];
        const size_t base = ((size_t)b_ * S_ + (size_t)qt * 64 + r) * D_ + h_ * HD_;
        float4 w;
        w.x = o[i][0] * inv; w.y = o[i][1] * inv;
        w.z = o[i][2] * inv; w.w = o[i][3] * inv;
        *(float4*)&ctx[base + (tx << 2)] = w;
    }
}

// ---------------------------------------------------------------------------
extern "C" void kernel_launch(void* const* d_in, const int* in_sizes, int n_in,
                              void* d_out, int out_size)
{
    const float* x  = (const float*)d_in[0];
    const float* Wq = (const float*)d_in[1];
    const float* bq = (const float*)d_in[2];
    const float* Wk = (const float*)d_in[3];
    const float* bk = (const float*)d_in[4];
    const float* Wv = (const float*)d_in[5];
    const float* bv = (const float*)d_in[6];
    const float* Wo = (const float*)d_in[7];
    const float* bo = (const float*)d_in[8];
    float* out = (float*)d_out;

    float *q, *k, *v, *c;
    cudaGetSymbolAddress((void**)&q, gQ);
    cudaGetSymbolAddress((void**)&k, gK);
    cudaGetSymbolAddress((void**)&v, gV);
    cudaGetSymbolAddress((void**)&c, gCtx);

    cudaFuncSetAttribute(attn_kernel,
                         cudaFuncAttributeMaxDynamicSharedMemorySize,
                         ATTN_SMEM_BYTES);

    const dim3 gblk(D_ / 64, M_ / 64);   // (12, 128)
    gemm_kernel<<<gblk, 256>>>(x, Wq, bq, q, 0.125f, 1);   // 1/sqrt(64) folded into Q
    gemm_kernel<<<gblk, 256>>>(x, Wk, bk, k, 1.0f, 1);
    gemm_kernel<<<gblk, 256>>>(x, Wv, bv, v, 1.0f, 1);

    attn_kernel<<<dim3(S_ / 64, B_ * H_), 256, ATTN_SMEM_BYTES>>>(q, k, v, c);

    gemm_kernel<<<gblk, 256>>>(c, Wo, bo, out, 1.0f, 0);
}

// round 2
// speedup vs baseline: 1.6123x; 1.6123x over previous
#include <cuda_runtime.h>
#include <math.h>
#include <stdint.h>

#define B_  2
#define S_  4096
#define D_  768
#define H_  12
#define HD_ 64
#define M_  (B_ * S_)   // 8192

// Scratch buffers (allocation-free rule: __device__ globals)
__device__ float gQ[(size_t)B_ * H_ * S_ * HD_];   // [B,H,S,HD], pre-scaled by 1/8
__device__ float gK[(size_t)B_ * H_ * S_ * HD_];
__device__ float gV[(size_t)B_ * H_ * S_ * HD_];
__device__ float gCtx[(size_t)B_ * S_ * D_];

// ---------------------------------------------------------------------------
// tf32 helpers
// ---------------------------------------------------------------------------
__device__ __forceinline__ uint32_t to_tf32(float v) {
    uint32_t t;
    asm("cvt.rna.tf32.f32 %0, %1;" : "=r"(t) : "f"(v));
    return t;
}

// D += A * B  (m16n8k8, tf32, row.col)
__device__ __forceinline__ void mma_tf32(float* d, const uint32_t* a, const uint32_t* b) {
    asm volatile(
        "mma.sync.aligned.m16n8k8.row.col.f32.tf32.tf32.f32 "
        "{%0,%1,%2,%3}, {%4,%5,%6,%7}, {%8,%9}, {%0,%1,%2,%3};\n"
        : "+f"(d[0]), "+f"(d[1]), "+f"(d[2]), "+f"(d[3])
        : "r"(a[0]), "r"(a[1]), "r"(a[2]), "r"(a[3]), "r"(b[0]), "r"(b[1]));
}

// Fragment-permuted smem layouts:
//  A-frag (m16 x k8):  lane = ((r&7)<<2)|(kc&3), idx = (r>>3)|(((kc&7)>>2)<<1)
//  B-frag (k8 x n8):   lane = ((c&7)<<2)|(kc&3), idx = (kc&7)>>2
// storage: A: [kstep][mtile][lane][4] floats;  B: [kstep][ntile][lane][2] floats

// ---------------------------------------------------------------------------
// tf32 SGEMM: out = (X @ W^T + bias) * scale
//   X: [M_, D_] row-major (A, k-major), W: [D_, D_] row-major (B col-major: W[n][k])
// Tile 128m x 64n x 32k, 256 threads, 8 warps (4m x 2n), warp = 32m x 32n.
// ---------------------------------------------------------------------------
#define GEMM_NK (D_ / 32)   // 24

__global__ void __launch_bounds__(256) gemm_tf32_kernel(
    const float* __restrict__ X, const float* __restrict__ W,
    const float* __restrict__ bias, float* __restrict__ out,
    float scale, int scatter)
{
    __shared__ float sA[4 * 8 * 32 * 4];   // 4096 floats: [ks4][mt8][lane][4]
    __shared__ float sB[4 * 8 * 32 * 2];   // 2048 floats: [ks4][nt8][lane][2]

    const int tid  = threadIdx.x;
    const int lane = tid & 31;
    const int wid  = tid >> 5;
    const int wm   = wid >> 1;   // 0..3
    const int wn   = wid & 1;    // 0..1
    const int m0   = blockIdx.y << 7;
    const int n0   = blockIdx.x << 6;

    // global load indexing
    const int arow = tid >> 1;               // 0..127
    const int akb  = (tid & 1) << 4;         // 0,16
    const int brow = tid >> 2;               // 0..63
    const int bkb  = (tid & 3) << 3;         // 0,8,16,24
    const float* xp = X + (size_t)(m0 + arow) * D_ + akb;
    const float* wp = W + (size_t)(n0 + brow) * D_ + bkb;

    float4 ra[4], rb[2];
#pragma unroll
    for (int u = 0; u < 4; u++) ra[u] = *(const float4*)(xp + u * 4);
#pragma unroll
    for (int u = 0; u < 2; u++) rb[u] = *(const float4*)(wp + u * 4);

    float acc[2][4][4] = {};

    for (int kt = 0; kt < GEMM_NK; kt++) {
        // store prefetched tile into permuted smem (tf32-rounded)
        {
            const int mt = arow >> 4, r = arow & 15;
            const int lb = (r & 7) << 2;
            const int ib = (r >> 3);
#pragma unroll
            for (int u = 0; u < 4; u++) {
                const int k = akb + u * 4;           // multiple of 4
                const int ks = k >> 3;
                const int idx = ib | (((k & 7) >> 2) << 1);
                float* dst = &sA[(((ks << 3) + mt) << 7) + idx];
                const float* f = (const float*)&ra[u];
#pragma unroll
                for (int e = 0; e < 4; e++)
                    dst[(lb + e) << 2] = __uint_as_float(to_tf32(f[e]));
            }
            const int nt = brow >> 3, c = brow & 7;
            const int lb2 = c << 2;
#pragma unroll
            for (int u = 0; u < 2; u++) {
                const int k = bkb + u * 4;
                const int ks = k >> 3;
                const int idx = (k & 7) >> 2;
                float* dst = &sB[(((ks << 3) + nt) << 6) + idx];
                const float* f = (const float*)&rb[u];
#pragma unroll
                for (int e = 0; e < 4; e++)
                    dst[(lb2 + e) << 1] = __uint_as_float(to_tf32(f[e]));
            }
        }
        __syncthreads();

        if (kt + 1 < GEMM_NK) {
            const int ko = (kt + 1) * 32;
#pragma unroll
            for (int u = 0; u < 4; u++) ra[u] = *(const float4*)(xp + ko + u * 4);
#pragma unroll
            for (int u = 0; u < 2; u++) rb[u] = *(const float4*)(wp + ko + u * 4);
        }

#pragma unroll
        for (int ks = 0; ks < 4; ks++) {
            float4 av[2];
            float2 bv[4];
#pragma unroll
            for (int i = 0; i < 2; i++)
                av[i] = *(const float4*)&sA[(((ks << 3) + (wm << 1) + i) << 7) + (lane << 2)];
#pragma unroll
            for (int j = 0; j < 4; j++)
                bv[j] = *(const float2*)&sB[(((ks << 3) + (wn << 2) + j) << 6) + (lane << 1)];
#pragma unroll
            for (int i = 0; i < 2; i++)
#pragma unroll
                for (int j = 0; j < 4; j++)
                    mma_tf32(acc[i][j], (const uint32_t*)&av[i], (const uint32_t*)&bv[j]);
        }
        __syncthreads();
    }

    // epilogue
    const int qr = lane >> 2;
    const int qc = (lane & 3) << 1;
#pragma unroll
    for (int j = 0; j < 4; j++) {
        const int n = n0 + (wn << 5) + (j << 3) + qc;
        const float b0 = bias[n], b1 = bias[n + 1];
#pragma unroll
        for (int i = 0; i < 2; i++) {
#pragma unroll
            for (int h = 0; h < 2; h++) {   // h=0: rows qr, h=1: rows qr+8
                const int m = m0 + (wm << 5) + (i << 4) + qr + (h << 3);
                float2 v;
                v.x = (acc[i][j][h * 2 + 0] + b0) * scale;
                v.y = (acc[i][j][h * 2 + 1] + b1) * scale;
                if (scatter) {
                    const int bb = m >> 12, ss = m & 4095;
                    const int hh = n >> 6, hd = n & 63;
                    *(float2*)&out[(((size_t)(bb * H_ + hh) * S_ + ss) << 6) + hd] = v;
                } else {
                    *(float2*)&out[(size_t)m * D_ + n] = v;
                }
            }
        }
    }
}

// ---------------------------------------------------------------------------
// Flash attention with tf32 mma. 64q x 64kv tiles, 256 threads (8 warps:
// 4 in q x 2 in kv/hd). Online softmax in fp32, P rounded to tf32 for PV.
// ---------------------------------------------------------------------------
#define PS_STRIDE 68
#define ATTN_SMEM_FLOATS (3 * 4096 + 64 * PS_STRIDE + 3 * 64)
#define ATTN_SMEM_BYTES  (ATTN_SMEM_FLOATS * 4)

__global__ void __launch_bounds__(256) attn_kernel(
    const float* __restrict__ Qg, const float* __restrict__ Kg,
    const float* __restrict__ Vg, float* __restrict__ ctx)
{
    extern __shared__ float sm[];
    float* sQ   = sm;              // 4096: [ks8][mt4][lane][4]  (A-frags, k=hd)
    float* sK   = sQ + 4096;       // 4096: [ks8][nt8][lane][2]  (B-frags: n=kv, k=hd)
    float* sV   = sK + 4096;       // 4096: [ks8][nt8][lane][2]  (B-frags: n=hd, k=kv)
    float* Ps   = sV + 4096;       // 64 x 68
    float* mrow = Ps + 64 * PS_STRIDE;
    float* lrow = mrow + 64;
    float* crow = lrow + 64;

    const int tid  = threadIdx.x;
    const int lane = tid & 31;
    const int wid  = tid >> 5;
    const int wm   = wid >> 1;   // 0..3 : q block of 16
    const int wn   = wid & 1;    // 0..1 : kv/hd half of 32
    const int bh   = blockIdx.y;
    const int qt   = (int)(gridDim.x - 1) - (int)blockIdx.x;   // longest first

    const float* Qp = Qg + ((size_t)bh * S_ + (size_t)qt * 64) * HD_;
    const float* Kp = Kg + (size_t)bh * S_ * HD_;
    const float* Vp = Vg + (size_t)bh * S_ * HD_;

    // --- load Q into A-fragment layout (once) ---
    {
        const int q  = tid >> 2;            // 0..63
        const int kb = (tid & 3) << 4;      // 0,16,32,48
        const int mt = q >> 4, r = q & 15;
        const int lb = (r & 7) << 2;
        const int ib = r >> 3;
        const float* qp = Qp + (size_t)q * HD_ + kb;
#pragma unroll
        for (int u = 0; u < 4; u++) {
            const float4 f = *(const float4*)(qp + u * 4);
            const int k = kb + u * 4;
            const int ks = k >> 3;
            const int idx = ib | (((k & 7) >> 2) << 1);
            float* dst = &sQ[(((ks << 2) + mt) << 7) + idx];
            const float* fv = (const float*)&f;
#pragma unroll
            for (int e = 0; e < 4; e++)
                dst[(lb + e) << 2] = __uint_as_float(to_tf32(fv[e]));
        }
    }
    if (tid < 64) { mrow[tid] = -INFINITY; lrow[tid] = 0.0f; }

    float o[4][4] = {};   // [j: hd frag][c0..c3]
    __syncthreads();

    const int ntiles = qt + 1;
    for (int t = 0; t < ntiles; t++) {
        // --- load K tile into B-frag layout (n=kv, k=hd) ---
        {
            const int kv = tid >> 2;
            const int hb = (tid & 3) << 4;
            const int nt = kv >> 3, c = kv & 7;
            const float* kp = Kp + (size_t)(t * 64 + kv) * HD_ + hb;
#pragma unroll
            for (int u = 0; u < 4; u++) {
                const float4 f = *(const float4*)(kp + u * 4);
                const float* fv = (const float*)&f;
#pragma unroll
                for (int e = 0; e < 4; e++) {
                    const int hd = hb + u * 4 + e;
                    const int ks = hd >> 3;
                    const int ln = (c << 2) | (hd & 3);
                    const int idx = (hd & 7) >> 2;
                    sK[((((ks << 3) + nt) << 5) + ln) * 2 + idx] =
                        __uint_as_float(to_tf32(fv[e]));
                }
            }
        }
        // --- load V tile into B-frag layout (n=hd, k=kv) ---
        {
            const int kv = tid >> 2;
            const int hb = (tid & 3) << 4;
            const int ks = kv >> 3;
            const int idx = (kv & 7) >> 2;
            const int lkc = kv & 3;
            const float* vp = Vp + (size_t)(t * 64 + kv) * HD_ + hb;
#pragma unroll
            for (int u = 0; u < 4; u++) {
                const float4 f = *(const float4*)(vp + u * 4);
                const float* fv = (const float*)&f;
#pragma unroll
                for (int e = 0; e < 4; e++) {
                    const int hd = hb + u * 4 + e;
                    const int nt = hd >> 3, c = hd & 7;
                    const int ln = (c << 2) | lkc;
                    sV[((((ks << 3) + nt) << 5) + ln) * 2 + idx] =
                        __uint_as_float(to_tf32(fv[e]));
                }
            }
        }
        __syncthreads();

        // --- S = Q K^T over this warp's 16q x 32kv ---
        float s[4][4] = {};
#pragma unroll
        for (int ks = 0; ks < 8; ks++) {
            const float4 aq = *(const float4*)&sQ[(((ks << 2) + wm) << 7) + (lane << 2)];
            float2 bv[4];
#pragma unroll
            for (int j = 0; j < 4; j++)
                bv[j] = *(const float2*)&sK[(((ks << 3) + (wn << 2) + j) << 6) + (lane << 1)];
#pragma unroll
            for (int j = 0; j < 4; j++)
                mma_tf32(s[j], (const uint32_t*)&aq, (const uint32_t*)&bv[j]);
        }

        // --- mask diag tile, store S into Ps ---
        const bool diag = (t == qt);
        const int qr0 = (wm << 4) + (lane >> 2);
        const int kc0 = (wn << 5) + ((lane & 3) << 1);
#pragma unroll
        for (int j = 0; j < 4; j++) {
            const int kc = kc0 + (j << 3);
            float2 v0, v1;
            v0.x = (diag && kc     > qr0) ? -INFINITY : s[j][0];
            v0.y = (diag && kc + 1 > qr0) ? -INFINITY : s[j][1];
            const int qr1 = qr0 + 8;
            v1.x = (diag && kc     > qr1) ? -INFINITY : s[j][2];
            v1.y = (diag && kc + 1 > qr1) ? -INFINITY : s[j][3];
            *(float2*)&Ps[qr0 * PS_STRIDE + kc] = v0;
            *(float2*)&Ps[qr1 * PS_STRIDE + kc] = v1;
        }
        __syncthreads();

        // --- online softmax (4 lanes per row, 16-col segments), tf32-round P ---
        {
            const int r   = tid >> 2;
            const int seg = tid & 3;
            float* prow = Ps + r * PS_STRIDE + seg * 16;
            float mx = prow[0];
#pragma unroll
            for (int c = 1; c < 16; c++) mx = fmaxf(mx, prow[c]);
            mx = fmaxf(mx, __shfl_xor_sync(0xffffffffu, mx, 1));
            mx = fmaxf(mx, __shfl_xor_sync(0xffffffffu, mx, 2));
            const float mold = mrow[r];
            const float mnew = fmaxf(mold, mx);
            float sum = 0.0f;
#pragma unroll
            for (int c = 0; c < 16; c++) {
                const float p = __expf(prow[c] - mnew);
                const float pr = __uint_as_float(to_tf32(p));
                prow[c] = pr;
                sum += pr;
            }
            sum += __shfl_xor_sync(0xffffffffu, sum, 1);
            sum += __shfl_xor_sync(0xffffffffu, sum, 2);
            if (seg == 0) {
                const float cf = __expf(mold - mnew);
                crow[r] = cf;
                lrow[r] = lrow[r] * cf + sum;
                mrow[r] = mnew;
            }
        }
        __syncthreads();

        // --- rescale O, then O += P V ---
        {
            const float cf0 = crow[qr0];
            const float cf1 = crow[qr0 + 8];
#pragma unroll
            for (int j = 0; j < 4; j++) {
                o[j][0] *= cf0; o[j][1] *= cf0;
                o[j][2] *= cf1; o[j][3] *= cf1;
            }
        }
#pragma unroll
        for (int ks = 0; ks < 8; ks++) {
            // A-frag of P from Ps (values already tf32-rounded)
            uint32_t a[4];
            const int pr0 = (wm << 4) + (lane >> 2);
            const int pc  = (ks << 3) + (lane & 3);
            a[0] = __float_as_uint(Ps[pr0 * PS_STRIDE + pc]);
            a[1] = __float_as_uint(Ps[(pr0 + 8) * PS_STRIDE + pc]);
            a[2] = __float_as_uint(Ps[pr0 * PS_STRIDE + pc + 4]);
            a[3] = __float_as_uint(Ps[(pr0 + 8) * PS_STRIDE + pc + 4]);
            float2 bv[4];
#pragma unroll
            for (int j = 0; j < 4; j++)
                bv[j] = *(const float2*)&sV[(((ks << 3) + (wn << 2) + j) << 6) + (lane << 1)];
#pragma unroll
            for (int j = 0; j < 4; j++)
                mma_tf32(o[j], a, (const uint32_t*)&bv[j]);
        }
        __syncthreads();
    }

    // --- normalize and write ctx [B,S,D] ---
    {
        const int b_ = bh / H_;
        const int h_ = bh % H_;
        const int qr = (wm << 4) + (lane >> 2);
        const float inv0 = 1.0f / lrow[qr];
        const float inv1 = 1.0f / lrow[qr + 8];
        const size_t base0 = ((size_t)b_ * S_ + (size_t)qt * 64 + qr) * D_ + h_ * HD_;
        const size_t base1 = base0 + (size_t)8 * D_;
#pragma unroll
        for (int j = 0; j < 4; j++) {
            const int hd = (wn << 5) + (j << 3) + ((lane & 3) << 1);
            float2 w0, w1;
            w0.x = o[j][0] * inv0; w0.y = o[j][1] * inv0;
            w1.x = o[j][2] * inv1; w1.y = o[j][3] * inv1;
            *(float2*)&ctx[base0 + hd] = w0;
            *(float2*)&ctx[base1 + hd] = w1;
        }
    }
}

// ---------------------------------------------------------------------------
extern "C" void kernel_launch(void* const* d_in, const int* in_sizes, int n_in,
                              void* d_out, int out_size)
{
    const float* x  = (const float*)d_in[0];
    const float* Wq = (const float*)d_in[1];
    const float* bq = (const float*)d_in[2];
    const float* Wk = (const float*)d_in[3];
    const float* bk = (const float*)d_in[4];
    const float* Wv = (const float*)d_in[5];
    const float* bv = (const float*)d_in[6];
    const float* Wo = (const float*)d_in[7];
    const float* bo = (const float*)d_in[8];
    float* out = (float*)d_out;

    float *q, *k, *v, *c;
    cudaGetSymbolAddress((void**)&q, gQ);
    cudaGetSymbolAddress((void**)&k, gK);
    cudaGetSymbolAddress((void**)&v, gV);
    cudaGetSymbolAddress((void**)&c, gCtx);

    cudaFuncSetAttribute(attn_kernel,
                         cudaFuncAttributeMaxDynamicSharedMemorySize,
                         ATTN_SMEM_BYTES);

    const dim3 gblk(D_ / 64, M_ / 128);   // (12, 64)
    gemm_tf32_kernel<<<gblk, 256>>>(x, Wq, bq, q, 0.125f, 1);  // 1/sqrt(64) into Q
    gemm_tf32_kernel<<<gblk, 256>>>(x, Wk, bk, k, 1.0f, 1);
    gemm_tf32_kernel<<<gblk, 256>>>(x, Wv, bv, v, 1.0f, 1);

    attn_kernel<<<dim3(S_ / 64, B_ * H_), 256, ATTN_SMEM_BYTES>>>(q, k, v, c);

    gemm_tf32_kernel<<<gblk, 256>>>(c, Wo, bo, out, 1.0f, 0);
}

// round 4
// speedup vs baseline: 2.0833x; 1.2922x over previous
#include <cuda_runtime.h>
#include <math.h>
#include <stdint.h>

#define B_  2
#define S_  4096
#define D_  768
#define H_  12
#define HD_ 64
#define M_  (B_ * S_)   // 8192

// Scratch (allocation-free rule: __device__ globals)
__device__ float gQ[(size_t)B_ * H_ * S_ * HD_];   // [B,H,S,HD], scaled by log2e/8
__device__ float gK[(size_t)B_ * H_ * S_ * HD_];
__device__ float gV[(size_t)B_ * H_ * S_ * HD_];
__device__ float gCtx[(size_t)B_ * S_ * D_];

// ---------------------------------------------------------------------------
__device__ __forceinline__ uint32_t to_tf32(float v) {
    uint32_t t;
    asm("cvt.rna.tf32.f32 %0, %1;" : "=r"(t) : "f"(v));
    return t;
}
__device__ __forceinline__ float ex2f(float x) {
    float y;
    asm("ex2.approx.ftz.f32 %0, %1;" : "=f"(y) : "f"(x));
    return y;
}
// D += A * B  (m16n8k8, tf32, row.col)
__device__ __forceinline__ void mma_tf32(float* d, const uint32_t* a, const uint32_t* b) {
    asm volatile(
        "mma.sync.aligned.m16n8k8.row.col.f32.tf32.tf32.f32 "
        "{%0,%1,%2,%3}, {%4,%5,%6,%7}, {%8,%9}, {%0,%1,%2,%3};\n"
        : "+f"(d[0]), "+f"(d[1]), "+f"(d[2]), "+f"(d[3])
        : "r"(a[0]), "r"(a[1]), "r"(a[2]), "r"(a[3]), "r"(b[0]), "r"(b[1]));
}

// ---------------------------------------------------------------------------
// tf32 GEMM: out = (X @ W^T + bias) * scale.
// Tile 128m x 64n x 32k, 256 thr, 8 warps (4m x 2n), warp 32m x 32n.
// Raw smem tiles with stride 36 (pad 4): frag gathers bank-conflict-free.
// ---------------------------------------------------------------------------
#define XSTR 36
__global__ void __launch_bounds__(256) gemm_tf32_kernel(
    const float* __restrict__ X, const float* __restrict__ W,
    const float* __restrict__ bias, float* __restrict__ out,
    float scale, int scatter)
{
    __shared__ float sX[128 * XSTR];
    __shared__ float sW[64 * XSTR];

    const int tid  = threadIdx.x;
    const int l    = tid & 31;
    const int wid  = tid >> 5;
    const int wm   = wid >> 1;
    const int wn   = wid & 1;
    const int r0   = l >> 2;
    const int c0   = l & 3;
    const int m0   = blockIdx.y << 7;
    const int n0   = blockIdx.x << 6;

    const int xr = tid >> 1, xc = (tid & 1) << 4;
    const float* xp = X + (size_t)(m0 + xr) * D_ + xc;
    const float* wp = W + (size_t)(n0 + (tid >> 1)) * D_ + ((tid & 1) << 4);

    float4 rx[4], rw[4];
#pragma unroll
    for (int u = 0; u < 4; u++) rx[u] = *(const float4*)(xp + 4 * u);
    if (tid < 128) {
#pragma unroll
        for (int u = 0; u < 4; u++) rw[u] = *(const float4*)(wp + 4 * u);
    }

    float acc[2][4][4] = {};

    for (int kt = 0; kt < D_ / 32; kt++) {
        {
            float* dx = &sX[xr * XSTR + xc];
#pragma unroll
            for (int u = 0; u < 4; u++) {
                float4 f;
                f.x = __uint_as_float(to_tf32(rx[u].x));
                f.y = __uint_as_float(to_tf32(rx[u].y));
                f.z = __uint_as_float(to_tf32(rx[u].z));
                f.w = __uint_as_float(to_tf32(rx[u].w));
                *(float4*)(dx + 4 * u) = f;
            }
            if (tid < 128) {
                float* dw = &sW[(tid >> 1) * XSTR + ((tid & 1) << 4)];
#pragma unroll
                for (int u = 0; u < 4; u++) {
                    float4 f;
                    f.x = __uint_as_float(to_tf32(rw[u].x));
                    f.y = __uint_as_float(to_tf32(rw[u].y));
                    f.z = __uint_as_float(to_tf32(rw[u].z));
                    f.w = __uint_as_float(to_tf32(rw[u].w));
                    *(float4*)(dw + 4 * u) = f;
                }
            }
        }
        __syncthreads();

        if (kt + 1 < D_ / 32) {
            const int ko = (kt + 1) * 32;
#pragma unroll
            for (int u = 0; u < 4; u++) rx[u] = *(const float4*)(xp + ko + 4 * u);
            if (tid < 128) {
#pragma unroll
                for (int u = 0; u < 4; u++) rw[u] = *(const float4*)(wp + ko + 4 * u);
            }
        }

#pragma unroll
        for (int ks = 0; ks < 4; ks++) {
            const int kk = ks * 8 + c0;
            uint32_t a[2][4], b[4][2];
#pragma unroll
            for (int i = 0; i < 2; i++) {
                const float* ab = &sX[(wm * 32 + i * 16 + r0) * XSTR];
                a[i][0] = __float_as_uint(ab[kk]);
                a[i][1] = __float_as_uint(ab[8 * XSTR + kk]);
                a[i][2] = __float_as_uint(ab[kk + 4]);
                a[i][3] = __float_as_uint(ab[8 * XSTR + kk + 4]);
            }
#pragma unroll
            for (int j = 0; j < 4; j++) {
                const float* bb = &sW[(wn * 32 + j * 8 + r0) * XSTR];
                b[j][0] = __float_as_uint(bb[kk]);
                b[j][1] = __float_as_uint(bb[kk + 4]);
            }
#pragma unroll
            for (int i = 0; i < 2; i++)
#pragma unroll
                for (int j = 0; j < 4; j++)
                    mma_tf32(acc[i][j], a[i], b[j]);
        }
        __syncthreads();
    }

    // epilogue
    const int qr = l >> 2;
    const int qc = (l & 3) << 1;
#pragma unroll
    for (int j = 0; j < 4; j++) {
        const int n = n0 + (wn << 5) + (j << 3) + qc;
        const float b0 = bias[n], b1 = bias[n + 1];
#pragma unroll
        for (int i = 0; i < 2; i++) {
#pragma unroll
            for (int h = 0; h < 2; h++) {
                const int m = m0 + (wm << 5) + (i << 4) + qr + (h << 3);
                float2 v;
                v.x = (acc[i][j][h * 2 + 0] + b0) * scale;
                v.y = (acc[i][j][h * 2 + 1] + b1) * scale;
                if (scatter) {
                    const int bb = m >> 12, ss = m & 4095;
                    const int hh = n >> 6, hd = n & 63;
                    *(float2*)&out[(((size_t)(bb * H_ + hh) * S_ + ss) << 6) + hd] = v;
                } else {
                    *(float2*)&out[(size_t)m * D_ + n] = v;
                }
            }
        }
    }
}

// ---------------------------------------------------------------------------
// Flash attention: 64q x 64kv tiles, 128 threads, 4 warps x (16q x 64kv).
// Softmax fully in registers (rows warp-local). P via shuffles, no Ps smem.
// sK stride 68, sV stride 72: conflict-free frag gathers.
// Q pre-scaled by log2e/8 -> ex2 softmax.
// ---------------------------------------------------------------------------
#define KSTR 68
#define VSTR 72

__global__ void __launch_bounds__(128) attn_kernel(
    const float* __restrict__ Qg, const float* __restrict__ Kg,
    const float* __restrict__ Vg, float* __restrict__ ctx)
{
    __shared__ float sK[64 * KSTR];
    __shared__ float sV[64 * VSTR];

    const int tid = threadIdx.x;
    const int l   = tid & 31;
    const int w   = tid >> 5;
    const int r0  = l >> 2;
    const int c0  = l & 3;
    const int bh  = blockIdx.y;
    const int qt  = (int)(gridDim.x - 1) - (int)blockIdx.x;  // longest first
    const int q0  = qt * 64;
    const int wq  = w * 16;

    const float* Qp = Qg + ((size_t)bh * S_ + q0 + wq) * HD_;
    const float* Kp = Kg + (size_t)bh * S_ * HD_;
    const float* Vp = Vg + (size_t)bh * S_ * HD_;

    // Q A-frags in registers (once)
    uint32_t qf[8][4];
#pragma unroll
    for (int ks = 0; ks < 8; ks++) {
        const int hd = ks * 8 + c0;
        qf[ks][0] = to_tf32(Qp[(size_t)r0 * HD_ + hd]);
        qf[ks][1] = to_tf32(Qp[(size_t)(r0 + 8) * HD_ + hd]);
        qf[ks][2] = to_tf32(Qp[(size_t)r0 * HD_ + hd + 4]);
        qf[ks][3] = to_tf32(Qp[(size_t)(r0 + 8) * HD_ + hd + 4]);
    }

    float o[8][4] = {};
    float m0 = -INFINITY, m1 = -INFINITY, l0 = 0.0f, l1 = 0.0f;

    const int ldr = tid >> 1;            // 0..63
    const int ldc = (tid & 1) << 5;      // 0,32

    for (int t = 0; t <= qt; t++) {
        // --- load K/V tile -> tf32 -> padded raw smem ---
        {
            const float* kg = Kp + ((size_t)(t * 64 + ldr)) * HD_ + ldc;
            const float* vg = Vp + ((size_t)(t * 64 + ldr)) * HD_ + ldc;
            float* kd = &sK[ldr * KSTR + ldc];
            float* vd = &sV[ldr * VSTR + ldc];
#pragma unroll
            for (int i = 0; i < 8; i++) {
                const float4 f = *(const float4*)(kg + 4 * i);
                const float4 g = *(const float4*)(vg + 4 * i);
                float4 fc, gc;
                fc.x = __uint_as_float(to_tf32(f.x));
                fc.y = __uint_as_float(to_tf32(f.y));
                fc.z = __uint_as_float(to_tf32(f.z));
                fc.w = __uint_as_float(to_tf32(f.w));
                gc.x = __uint_as_float(to_tf32(g.x));
                gc.y = __uint_as_float(to_tf32(g.y));
                gc.z = __uint_as_float(to_tf32(g.z));
                gc.w = __uint_as_float(to_tf32(g.w));
                *(float4*)(kd + 4 * i) = fc;
                *(float4*)(vd + 4 * i) = gc;
            }
        }
        __syncthreads();

        // --- S = Q K^T : warp computes 16q x 64kv ---
        float s[8][4] = {};
#pragma unroll
        for (int ks = 0; ks < 8; ks++) {
            const int kk = ks * 8 + c0;
#pragma unroll
            for (int nt = 0; nt < 8; nt++) {
                const float* kb = &sK[(nt * 8 + r0) * KSTR];
                uint32_t b[2];
                b[0] = __float_as_uint(kb[kk]);
                b[1] = __float_as_uint(kb[kk + 4]);
                mma_tf32(s[nt], qf[ks], b);
            }
        }

        // --- causal mask (diagonal tile only) ---
        if (t == qt) {
            const int colb = 2 * c0;
            const int qlo  = wq + r0;
            const int qhi  = qlo + 8;
#pragma unroll
            for (int nt = 0; nt < 8; nt++) {
                const int kc = nt * 8 + colb;
                if (kc     > qlo) s[nt][0] = -INFINITY;
                if (kc + 1 > qlo) s[nt][1] = -INFINITY;
                if (kc     > qhi) s[nt][2] = -INFINITY;
                if (kc + 1 > qhi) s[nt][3] = -INFINITY;
            }
        }

        // --- online softmax in registers ---
        float mx0 = -INFINITY, mx1 = -INFINITY;
#pragma unroll
        for (int nt = 0; nt < 8; nt++) {
            mx0 = fmaxf(mx0, fmaxf(s[nt][0], s[nt][1]));
            mx1 = fmaxf(mx1, fmaxf(s[nt][2], s[nt][3]));
        }
        mx0 = fmaxf(mx0, __shfl_xor_sync(0xffffffffu, mx0, 1));
        mx0 = fmaxf(mx0, __shfl_xor_sync(0xffffffffu, mx0, 2));
        mx1 = fmaxf(mx1, __shfl_xor_sync(0xffffffffu, mx1, 1));
        mx1 = fmaxf(mx1, __shfl_xor_sync(0xffffffffu, mx1, 2));

        const float nm0 = fmaxf(m0, mx0);
        const float nm1 = fmaxf(m1, mx1);
        const float cf0 = ex2f(m0 - nm0);
        const float cf1 = ex2f(m1 - nm1);

        float sum0 = 0.0f, sum1 = 0.0f;
#pragma unroll
        for (int nt = 0; nt < 8; nt++) {
            s[nt][0] = ex2f(s[nt][0] - nm0);
            s[nt][1] = ex2f(s[nt][1] - nm0);
            s[nt][2] = ex2f(s[nt][2] - nm1);
            s[nt][3] = ex2f(s[nt][3] - nm1);
            sum0 += s[nt][0] + s[nt][1];
            sum1 += s[nt][2] + s[nt][3];
        }
        sum0 += __shfl_xor_sync(0xffffffffu, sum0, 1);
        sum0 += __shfl_xor_sync(0xffffffffu, sum0, 2);
        sum1 += __shfl_xor_sync(0xffffffffu, sum1, 1);
        sum1 += __shfl_xor_sync(0xffffffffu, sum1, 2);

        l0 = l0 * cf0 + sum0;  m0 = nm0;
        l1 = l1 * cf1 + sum1;  m1 = nm1;

#pragma unroll
        for (int nt = 0; nt < 8; nt++) {
            o[nt][0] *= cf0; o[nt][1] *= cf0;
            o[nt][2] *= cf1; o[nt][3] *= cf1;
        }

        // --- O += P V : P C-frag -> A-frag via shuffles ---
        const int sl0 = (l & ~3) | (c0 >> 1);
        const int sl2 = sl0 + 2;
        const bool hp = (c0 & 1) != 0;
#pragma unroll
        for (int ks = 0; ks < 8; ks++) {
            const float v0a = __shfl_sync(0xffffffffu, s[ks][0], sl0);
            const float v0b = __shfl_sync(0xffffffffu, s[ks][1], sl0);
            const float v1a = __shfl_sync(0xffffffffu, s[ks][2], sl0);
            const float v1b = __shfl_sync(0xffffffffu, s[ks][3], sl0);
            const float v2a = __shfl_sync(0xffffffffu, s[ks][0], sl2);
            const float v2b = __shfl_sync(0xffffffffu, s[ks][1], sl2);
            const float v3a = __shfl_sync(0xffffffffu, s[ks][2], sl2);
            const float v3b = __shfl_sync(0xffffffffu, s[ks][3], sl2);
            uint32_t a[4];
            a[0] = to_tf32(hp ? v0b : v0a);
            a[1] = to_tf32(hp ? v1b : v1a);
            a[2] = to_tf32(hp ? v2b : v2a);
            a[3] = to_tf32(hp ? v3b : v3a);

            const float* vb0 = &sV[(ks * 8 + c0) * VSTR];
            const float* vb1 = &sV[(ks * 8 + c0 + 4) * VSTR];
#pragma unroll
            for (int nt = 0; nt < 8; nt++) {
                uint32_t b[2];
                b[0] = __float_as_uint(vb0[nt * 8 + r0]);
                b[1] = __float_as_uint(vb1[nt * 8 + r0]);
                mma_tf32(o[nt], a, b);
            }
        }
        __syncthreads();
    }

    // --- normalize + write ctx [B,S,D] ---
    {
        const int b_ = bh / H_;
        const int h_ = bh % H_;
        const float inv0 = 1.0f / l0;
        const float inv1 = 1.0f / l1;
        const size_t base0 = ((size_t)b_ * S_ + q0 + wq + r0) * D_ + h_ * HD_;
        const size_t base1 = base0 + (size_t)8 * D_;
#pragma unroll
        for (int nt = 0; nt < 8; nt++) {
            float2 w0, w1;
            w0.x = o[nt][0] * inv0; w0.y = o[nt][1] * inv0;
            w1.x = o[nt][2] * inv1; w1.y = o[nt][3] * inv1;
            *(float2*)&ctx[base0 + nt * 8 + 2 * c0] = w0;
            *(float2*)&ctx[base1 + nt * 8 + 2 * c0] = w1;
        }
    }
}

// ---------------------------------------------------------------------------
extern "C" void kernel_launch(void* const* d_in, const int* in_sizes, int n_in,
                              void* d_out, int out_size)
{
    const float* x  = (const float*)d_in[0];
    const float* Wq = (const float*)d_in[1];
    const float* bq = (const float*)d_in[2];
    const float* Wk = (const float*)d_in[3];
    const float* bk = (const float*)d_in[4];
    const float* Wv = (const float*)d_in[5];
    const float* bv = (const float*)d_in[6];
    const float* Wo = (const float*)d_in[7];
    const float* bo = (const float*)d_in[8];
    float* out = (float*)d_out;

    float *q, *k, *v, *c;
    cudaGetSymbolAddress((void**)&q, gQ);
    cudaGetSymbolAddress((void**)&k, gK);
    cudaGetSymbolAddress((void**)&v, gV);
    cudaGetSymbolAddress((void**)&c, gCtx);

    const dim3 gblk(D_ / 64, M_ / 128);   // (12, 64)
    // fold 1/sqrt(64) * log2(e) into Q so softmax uses ex2
    gemm_tf32_kernel<<<gblk, 256>>>(x, Wq, bq, q, 0.125f * 1.4426950408889634f, 1);
    gemm_tf32_kernel<<<gblk, 256>>>(x, Wk, bk, k, 1.0f, 1);
    gemm_tf32_kernel<<<gblk, 256>>>(x, Wv, bv, v, 1.0f, 1);

    attn_kernel<<<dim3(S_ / 64, B_ * H_), 128>>>(q, k, v, c);

    gemm_tf32_kernel<<<gblk, 256>>>(c, Wo, bo, out, 1.0f, 0);
}

// round 7
// speedup vs baseline: 2.4208x; 1.1620x over previous
#include <cuda_runtime.h>
#include <math.h>
#include <stdint.h>

#define B_  2
#define S_  4096
#define D_  768
#define H_  12
#define HD_ 64
#define M_  (B_ * S_)   // 8192

// Scratch (allocation-free rule: __device__ globals)
__device__ float gQ[(size_t)B_ * H_ * S_ * HD_];   // [B,H,S,HD], scaled by log2e/8
__device__ float gK[(size_t)B_ * H_ * S_ * HD_];
__device__ float gV[(size_t)B_ * H_ * S_ * HD_];
__device__ float gCtx[(size_t)B_ * S_ * D_];

// ---------------------------------------------------------------------------
__device__ __forceinline__ uint32_t to_tf32(float v) {
    uint32_t t;
    asm("cvt.rna.tf32.f32 %0, %1;" : "=r"(t) : "f"(v));
    return t;
}
__device__ __forceinline__ float ex2f(float x) {
    float y;
    asm("ex2.approx.ftz.f32 %0, %1;" : "=f"(y) : "f"(x));
    return y;
}
// D += A * B  (m16n8k8, tf32, row.col)
__device__ __forceinline__ void mma_tf32(float* d, const uint32_t* a, const uint32_t* b) {
    asm volatile(
        "mma.sync.aligned.m16n8k8.row.col.f32.tf32.tf32.f32 "
        "{%0,%1,%2,%3}, {%4,%5,%6,%7}, {%8,%9}, {%0,%1,%2,%3};\n"
        : "+f"(d[0]), "+f"(d[1]), "+f"(d[2]), "+f"(d[3])
        : "r"(a[0]), "r"(a[1]), "r"(a[2]), "r"(a[3]), "r"(b[0]), "r"(b[1]));
}

// ---------------------------------------------------------------------------
// tf32 GEMM (unchanged from R4): out = (X @ W^T + bias) * scale.
// ---------------------------------------------------------------------------
#define XSTR 36
__global__ void __launch_bounds__(256) gemm_tf32_kernel(
    const float* __restrict__ X, const float* __restrict__ W,
    const float* __restrict__ bias, float* __restrict__ out,
    float scale, int scatter)
{
    __shared__ float sX[128 * XSTR];
    __shared__ float sW[64 * XSTR];

    const int tid  = threadIdx.x;
    const int l    = tid & 31;
    const int wid  = tid >> 5;
    const int wm   = wid >> 1;
    const int wn   = wid & 1;
    const int r0   = l >> 2;
    const int c0   = l & 3;
    const int m0   = blockIdx.y << 7;
    const int n0   = blockIdx.x << 6;

    const int xr = tid >> 1, xc = (tid & 1) << 4;
    const float* xp = X + (size_t)(m0 + xr) * D_ + xc;
    const float* wp = W + (size_t)(n0 + (tid >> 1)) * D_ + ((tid & 1) << 4);

    float4 rx[4], rw[4];
#pragma unroll
    for (int u = 0; u < 4; u++) rx[u] = *(const float4*)(xp + 4 * u);
    if (tid < 128) {
#pragma unroll
        for (int u = 0; u < 4; u++) rw[u] = *(const float4*)(wp + 4 * u);
    }

    float acc[2][4][4] = {};

    for (int kt = 0; kt < D_ / 32; kt++) {
        {
            float* dx = &sX[xr * XSTR + xc];
#pragma unroll
            for (int u = 0; u < 4; u++) {
                float4 f;
                f.x = __uint_as_float(to_tf32(rx[u].x));
                f.y = __uint_as_float(to_tf32(rx[u].y));
                f.z = __uint_as_float(to_tf32(rx[u].z));
                f.w = __uint_as_float(to_tf32(rx[u].w));
                *(float4*)(dx + 4 * u) = f;
            }
            if (tid < 128) {
                float* dw = &sW[(tid >> 1) * XSTR + ((tid & 1) << 4)];
#pragma unroll
                for (int u = 0; u < 4; u++) {
                    float4 f;
                    f.x = __uint_as_float(to_tf32(rw[u].x));
                    f.y = __uint_as_float(to_tf32(rw[u].y));
                    f.z = __uint_as_float(to_tf32(rw[u].z));
                    f.w = __uint_as_float(to_tf32(rw[u].w));
                    *(float4*)(dw + 4 * u) = f;
                }
            }
        }
        __syncthreads();

        if (kt + 1 < D_ / 32) {
            const int ko = (kt + 1) * 32;
#pragma unroll
            for (int u = 0; u < 4; u++) rx[u] = *(const float4*)(xp + ko + 4 * u);
            if (tid < 128) {
#pragma unroll
                for (int u = 0; u < 4; u++) rw[u] = *(const float4*)(wp + ko + 4 * u);
            }
        }

#pragma unroll
        for (int ks = 0; ks < 4; ks++) {
            const int kk = ks * 8 + c0;
            uint32_t a[2][4], b[4][2];
#pragma unroll
            for (int i = 0; i < 2; i++) {
                const float* ab = &sX[(wm * 32 + i * 16 + r0) * XSTR];
                a[i][0] = __float_as_uint(ab[kk]);
                a[i][1] = __float_as_uint(ab[8 * XSTR + kk]);
                a[i][2] = __float_as_uint(ab[kk + 4]);
                a[i][3] = __float_as_uint(ab[8 * XSTR + kk + 4]);
            }
#pragma unroll
            for (int j = 0; j < 4; j++) {
                const float* bb = &sW[(wn * 32 + j * 8 + r0) * XSTR];
                b[j][0] = __float_as_uint(bb[kk]);
                b[j][1] = __float_as_uint(bb[kk + 4]);
            }
#pragma unroll
            for (int i = 0; i < 2; i++)
#pragma unroll
                for (int j = 0; j < 4; j++)
                    mma_tf32(acc[i][j], a[i], b[j]);
        }
        __syncthreads();
    }

    const int qr = l >> 2;
    const int qc = (l & 3) << 1;
#pragma unroll
    for (int j = 0; j < 4; j++) {
        const int n = n0 + (wn << 5) + (j << 3) + qc;
        const float b0 = bias[n], b1 = bias[n + 1];
#pragma unroll
        for (int i = 0; i < 2; i++) {
#pragma unroll
            for (int h = 0; h < 2; h++) {
                const int m = m0 + (wm << 5) + (i << 4) + qr + (h << 3);
                float2 v;
                v.x = (acc[i][j][h * 2 + 0] + b0) * scale;
                v.y = (acc[i][j][h * 2 + 1] + b1) * scale;
                if (scatter) {
                    const int bb = m >> 12, ss = m & 4095;
                    const int hh = n >> 6, hd = n & 63;
                    *(float2*)&out[(((size_t)(bb * H_ + hh) * S_ + ss) << 6) + hd] = v;
                } else {
                    *(float2*)&out[(size_t)m * D_ + n] = v;
                }
            }
        }
    }
}

// ---------------------------------------------------------------------------
// Flash attention v3 (fixed): CTA = 128q x 64kv, 128 threads, 4 warps x 32q.
// kv-chunk-fused: per 8-kv chunk do QK -> no-max softmax -> shuffle P -> PV.
// lsum is per-lane partial (2 cols/chunk); quad-reduced ONCE at the end
// (this was the R6 NaN bug: missing reduction -> lsum=0 on fully-masked
// lanes of the qt=0 diagonal CTA -> inf * 0 = NaN).
// ---------------------------------------------------------------------------
#define KSTR 68
#define VSTR 72

__global__ void __launch_bounds__(128) attn_kernel(
    const float* __restrict__ Qg, const float* __restrict__ Kg,
    const float* __restrict__ Vg, float* __restrict__ ctx)
{
    __shared__ float sK[64 * KSTR];
    __shared__ float sV[64 * VSTR];

    const int tid = threadIdx.x;
    const int l   = tid & 31;
    const int w   = tid >> 5;
    const int r0  = l >> 2;
    const int c0  = l & 3;
    const int bh  = blockIdx.y;
    const int qt  = (int)(gridDim.x - 1) - (int)blockIdx.x;  // longest first
    const int q0  = qt * 128;
    const int wq  = w * 32;

    const float* Qp = Qg + ((size_t)bh * S_ + q0 + wq) * HD_;
    const float* Kp = Kg + (size_t)bh * S_ * HD_;
    const float* Vp = Vg + (size_t)bh * S_ * HD_;

    // Q A-frags in registers: 2 groups of 16 rows
    uint32_t qf[2][8][4];
#pragma unroll
    for (int g = 0; g < 2; g++) {
        const float* qg_ = Qp + (size_t)(g * 16) * HD_;
#pragma unroll
        for (int ks = 0; ks < 8; ks++) {
            const int hd = ks * 8 + c0;
            qf[g][ks][0] = to_tf32(qg_[(size_t)r0 * HD_ + hd]);
            qf[g][ks][1] = to_tf32(qg_[(size_t)(r0 + 8) * HD_ + hd]);
            qf[g][ks][2] = to_tf32(qg_[(size_t)r0 * HD_ + hd + 4]);
            qf[g][ks][3] = to_tf32(qg_[(size_t)(r0 + 8) * HD_ + hd + 4]);
        }
    }

    float o[2][8][4] = {};
    float lsum[2][2] = {};

    const int ldr = tid >> 1;            // 0..63
    const int ldc = (tid & 1) << 5;      // 0,32

    // shuffle constants for P C-frag -> A-frag
    const int sl0 = (l & ~3) | (c0 >> 1);
    const int sl2 = sl0 + 2;
    const bool hp = (c0 & 1) != 0;

    const int ntiles = 2 * qt + 2;
    for (int t = 0; t < ntiles; t++) {
        // --- stage K/V tile -> tf32 -> padded raw smem ---
        {
            const float* kg = Kp + ((size_t)(t * 64 + ldr)) * HD_ + ldc;
            const float* vg = Vp + ((size_t)(t * 64 + ldr)) * HD_ + ldc;
            float* kd = &sK[ldr * KSTR + ldc];
            float* vd = &sV[ldr * VSTR + ldc];
#pragma unroll
            for (int i = 0; i < 8; i++) {
                const float4 f = *(const float4*)(kg + 4 * i);
                const float4 g = *(const float4*)(vg + 4 * i);
                float4 fc, gc;
                fc.x = __uint_as_float(to_tf32(f.x));
                fc.y = __uint_as_float(to_tf32(f.y));
                fc.z = __uint_as_float(to_tf32(f.z));
                fc.w = __uint_as_float(to_tf32(f.w));
                gc.x = __uint_as_float(to_tf32(g.x));
                gc.y = __uint_as_float(to_tf32(g.y));
                gc.z = __uint_as_float(to_tf32(g.z));
                gc.w = __uint_as_float(to_tf32(g.w));
                *(float4*)(kd + 4 * i) = fc;
                *(float4*)(vd + 4 * i) = gc;
            }
        }
        __syncthreads();

        const bool need_mask = (t >= 2 * qt);

        // --- per 8-kv chunk: QK -> softmax -> PV ---
#pragma unroll
        for (int nt = 0; nt < 8; nt++) {
            // QK for this chunk: s[g] = Q_g x K_chunk^T
            float s[2][4] = {};
#pragma unroll
            for (int ks = 0; ks < 8; ks++) {
                const int kk = ks * 8 + c0;
                const float* kb = &sK[(nt * 8 + r0) * KSTR];
                uint32_t b[2];
                b[0] = __float_as_uint(kb[kk]);
                b[1] = __float_as_uint(kb[kk + 4]);
                mma_tf32(s[0], qf[0][ks], b);
                mma_tf32(s[1], qf[1][ks], b);
            }

            // no-max softmax piece: p = exp2(s), masked -> 0, tf32-rounded
            float p[2][4];
#pragma unroll
            for (int g = 0; g < 2; g++) {
                float p0 = ex2f(s[g][0]);
                float p1 = ex2f(s[g][1]);
                float p2 = ex2f(s[g][2]);
                float p3 = ex2f(s[g][3]);
                if (need_mask) {
                    const int kvb = t * 64 + nt * 8 + 2 * c0;
                    const int qlo = q0 + wq + g * 16 + r0;
                    const int qhi = qlo + 8;
                    if (kvb     > qlo) p0 = 0.0f;
                    if (kvb + 1 > qlo) p1 = 0.0f;
                    if (kvb     > qhi) p2 = 0.0f;
                    if (kvb + 1 > qhi) p3 = 0.0f;
                }
                p0 = __uint_as_float(to_tf32(p0));
                p1 = __uint_as_float(to_tf32(p1));
                p2 = __uint_as_float(to_tf32(p2));
                p3 = __uint_as_float(to_tf32(p3));
                lsum[g][0] += p0 + p1;
                lsum[g][1] += p2 + p3;
                p[g][0] = p0; p[g][1] = p1; p[g][2] = p2; p[g][3] = p3;
            }

            // P C-frag -> A-frag via shuffles (per group)
            uint32_t a[2][4];
#pragma unroll
            for (int g = 0; g < 2; g++) {
                const float v0a = __shfl_sync(0xffffffffu, p[g][0], sl0);
                const float v0b = __shfl_sync(0xffffffffu, p[g][1], sl0);
                const float v1a = __shfl_sync(0xffffffffu, p[g][2], sl0);
                const float v1b = __shfl_sync(0xffffffffu, p[g][3], sl0);
                const float v2a = __shfl_sync(0xffffffffu, p[g][0], sl2);
                const float v2b = __shfl_sync(0xffffffffu, p[g][1], sl2);
                const float v3a = __shfl_sync(0xffffffffu, p[g][2], sl2);
                const float v3b = __shfl_sync(0xffffffffu, p[g][3], sl2);
                a[g][0] = __float_as_uint(hp ? v0b : v0a);
                a[g][1] = __float_as_uint(hp ? v1b : v1a);
                a[g][2] = __float_as_uint(hp ? v2b : v2a);
                a[g][3] = __float_as_uint(hp ? v3b : v3a);
            }

            // PV for this chunk: O_g += P_chunk x V_chunk
            const float* vb0 = &sV[(nt * 8 + c0) * VSTR];
            const float* vb1 = &sV[(nt * 8 + c0 + 4) * VSTR];
#pragma unroll
            for (int ntv = 0; ntv < 8; ntv++) {
                uint32_t b[2];
                b[0] = __float_as_uint(vb0[ntv * 8 + r0]);
                b[1] = __float_as_uint(vb1[ntv * 8 + r0]);
                mma_tf32(o[0][ntv], a[0], b);
                mma_tf32(o[1][ntv], a[1], b);
            }
        }
        __syncthreads();
    }

    // --- quad-reduce row sums (R6 fix), normalize + write ctx [B,S,D] ---
    {
#pragma unroll
        for (int g = 0; g < 2; g++) {
#pragma unroll
            for (int hh = 0; hh < 2; hh++) {
                lsum[g][hh] += __shfl_xor_sync(0xffffffffu, lsum[g][hh], 1);
                lsum[g][hh] += __shfl_xor_sync(0xffffffffu, lsum[g][hh], 2);
            }
        }

        const int b_ = bh / H_;
        const int h_ = bh % H_;
#pragma unroll
        for (int g = 0; g < 2; g++) {
            const float inv0 = 1.0f / lsum[g][0];
            const float inv1 = 1.0f / lsum[g][1];
            const size_t base0 = ((size_t)b_ * S_ + q0 + wq + g * 16 + r0) * D_ + h_ * HD_;
            const size_t base1 = base0 + (size_t)8 * D_;
#pragma unroll
            for (int ntv = 0; ntv < 8; ntv++) {
                float2 w0, w1;
                w0.x = o[g][ntv][0] * inv0; w0.y = o[g][ntv][1] * inv0;
                w1.x = o[g][ntv][2] * inv1; w1.y = o[g][ntv][3] * inv1;
                *(float2*)&ctx[base0 + ntv * 8 + 2 * c0] = w0;
                *(float2*)&ctx[base1 + ntv * 8 + 2 * c0] = w1;
            }
        }
    }
}

// ---------------------------------------------------------------------------
extern "C" void kernel_launch(void* const* d_in, const int* in_sizes, int n_in,
                              void* d_out, int out_size)
{
    const float* x  = (const float*)d_in[0];
    const float* Wq = (const float*)d_in[1];
    const float* bq = (const float*)d_in[2];
    const float* Wk = (const float*)d_in[3];
    const float* bk = (const float*)d_in[4];
    const float* Wv = (const float*)d_in[5];
    const float* bv = (const float*)d_in[6];
    const float* Wo = (const float*)d_in[7];
    const float* bo = (const float*)d_in[8];
    float* out = (float*)d_out;

    float *q, *k, *v, *c;
    cudaGetSymbolAddress((void**)&q, gQ);
    cudaGetSymbolAddress((void**)&k, gK);
    cudaGetSymbolAddress((void**)&v, gV);
    cudaGetSymbolAddress((void**)&c, gCtx);

    const dim3 gblk(D_ / 64, M_ / 128);   // (12, 64)
    // fold 1/sqrt(64) * log2(e) into Q so softmax uses ex2
    gemm_tf32_kernel<<<gblk, 256>>>(x, Wq, bq, q, 0.125f * 1.4426950408889634f, 1);
    gemm_tf32_kernel<<<gblk, 256>>>(x, Wk, bk, k, 1.0f, 1);
    gemm_tf32_kernel<<<gblk, 256>>>(x, Wv, bv, v, 1.0f, 1);

    attn_kernel<<<dim3(S_ / 128, B_ * H_), 128>>>(q, k, v, c);

    gemm_tf32_kernel<<<gblk, 256>>>(c, Wo, bo, out, 1.0f, 0);
}

// round 8
// speedup vs baseline: 2.4223x; 1.0006x over previous
#include <cuda_runtime.h>
#include <math.h>
#include <stdint.h>

#define B_  2
#define S_  4096
#define D_  768
#define H_  12
#define HD_ 64
#define M_  (B_ * S_)   // 8192

// Scratch (allocation-free rule: __device__ globals)
__device__ float gQ[(size_t)B_ * H_ * S_ * HD_];   // [B,H,S,HD], scaled by log2e/8
__device__ float gK[(size_t)B_ * H_ * S_ * HD_];
__device__ float gV[(size_t)B_ * H_ * S_ * HD_];
__device__ float gCtx[(size_t)B_ * S_ * D_];

// ---------------------------------------------------------------------------
__device__ __forceinline__ uint32_t to_tf32(float v) {
    uint32_t t;
    asm("cvt.rna.tf32.f32 %0, %1;" : "=r"(t) : "f"(v));
    return t;
}
__device__ __forceinline__ float ex2f(float x) {
    float y;
    asm("ex2.approx.ftz.f32 %0, %1;" : "=f"(y) : "f"(x));
    return y;
}
// D += A * B  (m16n8k8, tf32, row.col)
__device__ __forceinline__ void mma_tf32(float* d, const uint32_t* a, const uint32_t* b) {
    asm volatile(
        "mma.sync.aligned.m16n8k8.row.col.f32.tf32.tf32.f32 "
        "{%0,%1,%2,%3}, {%4,%5,%6,%7}, {%8,%9}, {%0,%1,%2,%3};\n"
        : "+f"(d[0]), "+f"(d[1]), "+f"(d[2]), "+f"(d[3])
        : "r"(a[0]), "r"(a[1]), "r"(a[2]), "r"(a[3]), "r"(b[0]), "r"(b[1]));
}

// ---------------------------------------------------------------------------
// tf32 GEMM (unchanged from R4): out = (X @ W^T + bias) * scale.
// ---------------------------------------------------------------------------
#define XSTR 36
__global__ void __launch_bounds__(256) gemm_tf32_kernel(
    const float* __restrict__ X, const float* __restrict__ W,
    const float* __restrict__ bias, float* __restrict__ out,
    float scale, int scatter)
{
    __shared__ float sX[128 * XSTR];
    __shared__ float sW[64 * XSTR];

    const int tid  = threadIdx.x;
    const int l    = tid & 31;
    const int wid  = tid >> 5;
    const int wm   = wid >> 1;
    const int wn   = wid & 1;
    const int r0   = l >> 2;
    const int c0   = l & 3;
    const int m0   = blockIdx.y << 7;
    const int n0   = blockIdx.x << 6;

    const int xr = tid >> 1, xc = (tid & 1) << 4;
    const float* xp = X + (size_t)(m0 + xr) * D_ + xc;
    const float* wp = W + (size_t)(n0 + (tid >> 1)) * D_ + ((tid & 1) << 4);

    float4 rx[4], rw[4];
#pragma unroll
    for (int u = 0; u < 4; u++) rx[u] = *(const float4*)(xp + 4 * u);
    if (tid < 128) {
#pragma unroll
        for (int u = 0; u < 4; u++) rw[u] = *(const float4*)(wp + 4 * u);
    }

    float acc[2][4][4] = {};

    for (int kt = 0; kt < D_ / 32; kt++) {
        {
            float* dx = &sX[xr * XSTR + xc];
#pragma unroll
            for (int u = 0; u < 4; u++) {
                float4 f;
                f.x = __uint_as_float(to_tf32(rx[u].x));
                f.y = __uint_as_float(to_tf32(rx[u].y));
                f.z = __uint_as_float(to_tf32(rx[u].z));
                f.w = __uint_as_float(to_tf32(rx[u].w));
                *(float4*)(dx + 4 * u) = f;
            }
            if (tid < 128) {
                float* dw = &sW[(tid >> 1) * XSTR + ((tid & 1) << 4)];
#pragma unroll
                for (int u = 0; u < 4; u++) {
                    float4 f;
                    f.x = __uint_as_float(to_tf32(rw[u].x));
                    f.y = __uint_as_float(to_tf32(rw[u].y));
                    f.z = __uint_as_float(to_tf32(rw[u].z));
                    f.w = __uint_as_float(to_tf32(rw[u].w));
                    *(float4*)(dw + 4 * u) = f;
                }
            }
        }
        __syncthreads();

        if (kt + 1 < D_ / 32) {
            const int ko = (kt + 1) * 32;
#pragma unroll
            for (int u = 0; u < 4; u++) rx[u] = *(const float4*)(xp + ko + 4 * u);
            if (tid < 128) {
#pragma unroll
                for (int u = 0; u < 4; u++) rw[u] = *(const float4*)(wp + ko + 4 * u);
            }
        }

#pragma unroll
        for (int ks = 0; ks < 4; ks++) {
            const int kk = ks * 8 + c0;
            uint32_t a[2][4], b[4][2];
#pragma unroll
            for (int i = 0; i < 2; i++) {
                const float* ab = &sX[(wm * 32 + i * 16 + r0) * XSTR];
                a[i][0] = __float_as_uint(ab[kk]);
                a[i][1] = __float_as_uint(ab[8 * XSTR + kk]);
                a[i][2] = __float_as_uint(ab[kk + 4]);
                a[i][3] = __float_as_uint(ab[8 * XSTR + kk + 4]);
            }
#pragma unroll
            for (int j = 0; j < 4; j++) {
                const float* bb = &sW[(wn * 32 + j * 8 + r0) * XSTR];
                b[j][0] = __float_as_uint(bb[kk]);
                b[j][1] = __float_as_uint(bb[kk + 4]);
            }
#pragma unroll
            for (int i = 0; i < 2; i++)
#pragma unroll
                for (int j = 0; j < 4; j++)
                    mma_tf32(acc[i][j], a[i], b[j]);
        }
        __syncthreads();
    }

    const int qr = l >> 2;
    const int qc = (l & 3) << 1;
#pragma unroll
    for (int j = 0; j < 4; j++) {
        const int n = n0 + (wn << 5) + (j << 3) + qc;
        const float b0 = bias[n], b1 = bias[n + 1];
#pragma unroll
        for (int i = 0; i < 2; i++) {
#pragma unroll
            for (int h = 0; h < 2; h++) {
                const int m = m0 + (wm << 5) + (i << 4) + qr + (h << 3);
                float2 v;
                v.x = (acc[i][j][h * 2 + 0] + b0) * scale;
                v.y = (acc[i][j][h * 2 + 1] + b1) * scale;
                if (scatter) {
                    const int bb = m >> 12, ss = m & 4095;
                    const int hh = n >> 6, hd = n & 63;
                    *(float2*)&out[(((size_t)(bb * H_ + hh) * S_ + ss) << 6) + hd] = v;
                } else {
                    *(float2*)&out[(size_t)m * D_ + n] = v;
                }
            }
        }
    }
}

// ---------------------------------------------------------------------------
// Flash attention v3 (fixed): CTA = 128q x 64kv, 128 threads, 4 warps x 32q.
// kv-chunk-fused: per 8-kv chunk do QK -> no-max softmax -> shuffle P -> PV.
// lsum is per-lane partial (2 cols/chunk); quad-reduced ONCE at the end
// (this was the R6 NaN bug: missing reduction -> lsum=0 on fully-masked
// lanes of the qt=0 diagonal CTA -> inf * 0 = NaN).
// ---------------------------------------------------------------------------
#define KSTR 68
#define VSTR 72

__global__ void __launch_bounds__(128) attn_kernel(
    const float* __restrict__ Qg, const float* __restrict__ Kg,
    const float* __restrict__ Vg, float* __restrict__ ctx)
{
    __shared__ float sK[64 * KSTR];
    __shared__ float sV[64 * VSTR];

    const int tid = threadIdx.x;
    const int l   = tid & 31;
    const int w   = tid >> 5;
    const int r0  = l >> 2;
    const int c0  = l & 3;
    const int bh  = blockIdx.y;
    const int qt  = (int)(gridDim.x - 1) - (int)blockIdx.x;  // longest first
    const int q0  = qt * 128;
    const int wq  = w * 32;

    const float* Qp = Qg + ((size_t)bh * S_ + q0 + wq) * HD_;
    const float* Kp = Kg + (size_t)bh * S_ * HD_;
    const float* Vp = Vg + (size_t)bh * S_ * HD_;

    // Q A-frags in registers: 2 groups of 16 rows
    uint32_t qf[2][8][4];
#pragma unroll
    for (int g = 0; g < 2; g++) {
        const float* qg_ = Qp + (size_t)(g * 16) * HD_;
#pragma unroll
        for (int ks = 0; ks < 8; ks++) {
            const int hd = ks * 8 + c0;
            qf[g][ks][0] = to_tf32(qg_[(size_t)r0 * HD_ + hd]);
            qf[g][ks][1] = to_tf32(qg_[(size_t)(r0 + 8) * HD_ + hd]);
            qf[g][ks][2] = to_tf32(qg_[(size_t)r0 * HD_ + hd + 4]);
            qf[g][ks][3] = to_tf32(qg_[(size_t)(r0 + 8) * HD_ + hd + 4]);
        }
    }

    float o[2][8][4] = {};
    float lsum[2][2] = {};

    const int ldr = tid >> 1;            // 0..63
    const int ldc = (tid & 1) << 5;      // 0,32

    // shuffle constants for P C-frag -> A-frag
    const int sl0 = (l & ~3) | (c0 >> 1);
    const int sl2 = sl0 + 2;
    const bool hp = (c0 & 1) != 0;

    const int ntiles = 2 * qt + 2;
    for (int t = 0; t < ntiles; t++) {
        // --- stage K/V tile -> tf32 -> padded raw smem ---
        {
            const float* kg = Kp + ((size_t)(t * 64 + ldr)) * HD_ + ldc;
            const float* vg = Vp + ((size_t)(t * 64 + ldr)) * HD_ + ldc;
            float* kd = &sK[ldr * KSTR + ldc];
            float* vd = &sV[ldr * VSTR + ldc];
#pragma unroll
            for (int i = 0; i < 8; i++) {
                const float4 f = *(const float4*)(kg + 4 * i);
                const float4 g = *(const float4*)(vg + 4 * i);
                float4 fc, gc;
                fc.x = __uint_as_float(to_tf32(f.x));
                fc.y = __uint_as_float(to_tf32(f.y));
                fc.z = __uint_as_float(to_tf32(f.z));
                fc.w = __uint_as_float(to_tf32(f.w));
                gc.x = __uint_as_float(to_tf32(g.x));
                gc.y = __uint_as_float(to_tf32(g.y));
                gc.z = __uint_as_float(to_tf32(g.z));
                gc.w = __uint_as_float(to_tf32(g.w));
                *(float4*)(kd + 4 * i) = fc;
                *(float4*)(vd + 4 * i) = gc;
            }
        }
        __syncthreads();

        const bool need_mask = (t >= 2 * qt);

        // --- per 8-kv chunk: QK -> softmax -> PV ---
#pragma unroll
        for (int nt = 0; nt < 8; nt++) {
            // QK for this chunk: s[g] = Q_g x K_chunk^T
            float s[2][4] = {};
#pragma unroll
            for (int ks = 0; ks < 8; ks++) {
                const int kk = ks * 8 + c0;
                const float* kb = &sK[(nt * 8 + r0) * KSTR];
                uint32_t b[2];
                b[0] = __float_as_uint(kb[kk]);
                b[1] = __float_as_uint(kb[kk + 4]);
                mma_tf32(s[0], qf[0][ks], b);
                mma_tf32(s[1], qf[1][ks], b);
            }

            // no-max softmax piece: p = exp2(s), masked -> 0, tf32-rounded
            float p[2][4];
#pragma unroll
            for (int g = 0; g < 2; g++) {
                float p0 = ex2f(s[g][0]);
                float p1 = ex2f(s[g][1]);
                float p2 = ex2f(s[g][2]);
                float p3 = ex2f(s[g][3]);
                if (need_mask) {
                    const int kvb = t * 64 + nt * 8 + 2 * c0;
                    const int qlo = q0 + wq + g * 16 + r0;
                    const int qhi = qlo + 8;
                    if (kvb     > qlo) p0 = 0.0f;
                    if (kvb + 1 > qlo) p1 = 0.0f;
                    if (kvb     > qhi) p2 = 0.0f;
                    if (kvb + 1 > qhi) p3 = 0.0f;
                }
                p0 = __uint_as_float(to_tf32(p0));
                p1 = __uint_as_float(to_tf32(p1));
                p2 = __uint_as_float(to_tf32(p2));
                p3 = __uint_as_float(to_tf32(p3));
                lsum[g][0] += p0 + p1;
                lsum[g][1] += p2 + p3;
                p[g][0] = p0; p[g][1] = p1; p[g][2] = p2; p[g][3] = p3;
            }

            // P C-frag -> A-frag via shuffles (per group)
            uint32_t a[2][4];
#pragma unroll
            for (int g = 0; g < 2; g++) {
                const float v0a = __shfl_sync(0xffffffffu, p[g][0], sl0);
                const float v0b = __shfl_sync(0xffffffffu, p[g][1], sl0);
                const float v1a = __shfl_sync(0xffffffffu, p[g][2], sl0);
                const float v1b = __shfl_sync(0xffffffffu, p[g][3], sl0);
                const float v2a = __shfl_sync(0xffffffffu, p[g][0], sl2);
                const float v2b = __shfl_sync(0xffffffffu, p[g][1], sl2);
                const float v3a = __shfl_sync(0xffffffffu, p[g][2], sl2);
                const float v3b = __shfl_sync(0xffffffffu, p[g][3], sl2);
                a[g][0] = __float_as_uint(hp ? v0b : v0a);
                a[g][1] = __float_as_uint(hp ? v1b : v1a);
                a[g][2] = __float_as_uint(hp ? v2b : v2a);
                a[g][3] = __float_as_uint(hp ? v3b : v3a);
            }

            // PV for this chunk: O_g += P_chunk x V_chunk
            const float* vb0 = &sV[(nt * 8 + c0) * VSTR];
            const float* vb1 = &sV[(nt * 8 + c0 + 4) * VSTR];
#pragma unroll
            for (int ntv = 0; ntv < 8; ntv++) {
                uint32_t b[2];
                b[0] = __float_as_uint(vb0[ntv * 8 + r0]);
                b[1] = __float_as_uint(vb1[ntv * 8 + r0]);
                mma_tf32(o[0][ntv], a[0], b);
                mma_tf32(o[1][ntv], a[1], b);
            }
        }
        __syncthreads();
    }

    // --- quad-reduce row sums (R6 fix), normalize + write ctx [B,S,D] ---
    {
#pragma unroll
        for (int g = 0; g < 2; g++) {
#pragma unroll
            for (int hh = 0; hh < 2; hh++) {
                lsum[g][hh] += __shfl_xor_sync(0xffffffffu, lsum[g][hh], 1);
                lsum[g][hh] += __shfl_xor_sync(0xffffffffu, lsum[g][hh], 2);
            }
        }

        const int b_ = bh / H_;
        const int h_ = bh % H_;
#pragma unroll
        for (int g = 0; g < 2; g++) {
            const float inv0 = 1.0f / lsum[g][0];
            const float inv1 = 1.0f / lsum[g][1];
            const size_t base0 = ((size_t)b_ * S_ + q0 + wq + g * 16 + r0) * D_ + h_ * HD_;
            const size_t base1 = base0 + (size_t)8 * D_;
#pragma unroll
            for (int ntv = 0; ntv < 8; ntv++) {
                float2 w0, w1;
                w0.x = o[g][ntv][0] * inv0; w0.y = o[g][ntv][1] * inv0;
                w1.x = o[g][ntv][2] * inv1; w1.y = o[g][ntv][3] * inv1;
                *(float2*)&ctx[base0 + ntv * 8 + 2 * c0] = w0;
                *(float2*)&ctx[base1 + ntv * 8 + 2 * c0] = w1;
            }
        }
    }
}

// ---------------------------------------------------------------------------
extern "C" void kernel_launch(void* const* d_in, const int* in_sizes, int n_in,
                              void* d_out, int out_size)
{
    const float* x  = (const float*)d_in[0];
    const float* Wq = (const float*)d_in[1];
    const float* bq = (const float*)d_in[2];
    const float* Wk = (const float*)d_in[3];
    const float* bk = (const float*)d_in[4];
    const float* Wv = (const float*)d_in[5];
    const float* bv = (const float*)d_in[6];
    const float* Wo = (const float*)d_in[7];
    const float* bo = (const float*)d_in[8];
    float* out = (float*)d_out;

    float *q, *k, *v, *c;
    cudaGetSymbolAddress((void**)&q, gQ);
    cudaGetSymbolAddress((void**)&k, gK);
    cudaGetSymbolAddress((void**)&v, gV);
    cudaGetSymbolAddress((void**)&c, gCtx);

    const dim3 gblk(D_ / 64, M_ / 128);   // (12, 64)
    // fold 1/sqrt(64) * log2(e) into Q so softmax uses ex2
    gemm_tf32_kernel<<<gblk, 256>>>(x, Wq, bq, q, 0.125f * 1.4426950408889634f, 1);
    gemm_tf32_kernel<<<gblk, 256>>>(x, Wk, bk, k, 1.0f, 1);
    gemm_tf32_kernel<<<gblk, 256>>>(x, Wv, bv, v, 1.0f, 1);

    attn_kernel<<<dim3(S_ / 128, B_ * H_), 128>>>(q, k, v, c);

    gemm_tf32_kernel<<<gblk, 256>>>(c, Wo, bo, out, 1.0f, 0);
}